// round 16
// baseline (speedup 1.0000x reference)
#include <cuda_runtime.h>
#include <cuda_bf16.h>
#include <math.h>

// Problem constants
static constexpr int NB = 4096;   // batch
static constexpr int NL = 16;     // seq length
static constexpr int NH = 256;    // hidden
static constexpr int NLAT = 64;   // latent
static constexpr int NV = 800;    // vocab
static constexpr int NVP = 1024;  // padded vocab
static constexpr int STEPS = NL - 1;  // 15

// ---------------- packed f32x2 helpers ----------------
#define FFMA2(acc, a, b) asm("fma.rn.f32x2 %0, %1, %2, %0;" : "+l"(acc) : "l"(a), "l"(b))

static __device__ __forceinline__ float2 unpack2(unsigned long long v) {
    float2 f;
    asm("mov.b64 {%0, %1}, %2;" : "=f"(f.x), "=f"(f.y) : "l"(v));
    return f;
}

// ---------------- device scratch (allocation-free) ----------------
__device__ float g_mfwd[STEPS * NB * NH];
__device__ float g_mrev[STEPS * NB * NH];
// pair-interleaved weights: ull2 index kk*J + col  (kk = k/4)
__device__ ulonglong2 g_Wz4[512 * 256 / 4];
__device__ ulonglong2 g_Wh4[512 * 256 / 4];
__device__ ulonglong2 g_C4 [512 * 256 / 4];   // [Wr ; Ur]
__device__ ulonglong2 g_Wq4[320 * 256 / 4];
__device__ ulonglong2 g_Up4[576 * 256 / 4];
__device__ ulonglong2 g_Wo4[256 * NVP / 4];   // padded, zeros beyond 800
__device__ double g_qloss, g_ploss;
__device__ unsigned long long g_qcnt, g_pcnt;

// ---------------- init ----------------
__global__ void k_init() {
    if (threadIdx.x == 0) {
        g_qloss = 0.0; g_ploss = 0.0; g_qcnt = 0ULL; g_pcnt = 0ULL;
    }
}

// ---------------- single-launch repack ----------------
__global__ void k_repack_all(const float* __restrict__ Wz, const float* __restrict__ Wh,
                             const float* __restrict__ Wr, const float* __restrict__ Ur,
                             const float* __restrict__ Wq, const float* __restrict__ Up,
                             const float* __restrict__ Wo) {
    int idx = blockIdx.x * blockDim.x + threadIdx.x;
    const int n0 = 256 * 512, n1 = n0 + 256 * 512, n2 = n1 + 256 * 256,
              n3 = n2 + 256 * 256, n4 = n3 + 256 * 320, n5 = n4 + 256 * 576,
              n6 = n5 + NVP * 256;
    if (idx >= n6) return;
    if (idx >= n5) {
        idx -= n5;
        int jcol = idx / 256, k = idx % 256;
        ((float*)g_Wo4)[((k >> 2) * NVP + jcol) * 4 + (k & 3)] =
            (jcol < NV) ? Wo[jcol * 256 + k] : 0.f;
        return;
    }
    const float* src; float* dst; int J, K, koff;
    if      (idx < n0) { src = Wz; dst = (float*)g_Wz4; J = 256; K = 512; koff = 0; }
    else if (idx < n1) { src = Wh; dst = (float*)g_Wh4; J = 256; K = 512; koff = 0; idx -= n0; }
    else if (idx < n2) { src = Wr; dst = (float*)g_C4;  J = 256; K = 256; koff = 0; idx -= n1; }
    else if (idx < n3) { src = Ur; dst = (float*)g_C4;  J = 256; K = 256; koff = 256; idx -= n2; }
    else if (idx < n4) { src = Wq; dst = (float*)g_Wq4; J = 256; K = 320; koff = 0; idx -= n3; }
    else               { src = Up; dst = (float*)g_Up4; J = 256; K = 576; koff = 0; idx -= n4; }
    int jcol = idx / K, k = idx % K;
    int kk = k + koff;
    dst[((kk >> 2) * J + jcol) * 4 + (kk & 3)] = src[jcol * K + k];
}

// ---------------- 64-kk GEMM block: 8 rows x 2 cols per thread (R9 proven) ----------------
static __device__ __forceinline__ void gemm64x2(unsigned long long* acc,
                                                const ulonglong2* __restrict__ W,
                                                const ulonglong2* S,
                                                int c2, int rg8) {
    #pragma unroll 2
    for (int kk = 0; kk < 64; kk++) {
        ulonglong2 w0 = W[kk * NH + c2];
        ulonglong2 w1 = W[kk * NH + c2 + 128];
        #pragma unroll
        for (int r = 0; r < 8; r++) {
            ulonglong2 a = S[(rg8 + r) * 64 + kk];
            FFMA2(acc[r],     a.x, w0.x); FFMA2(acc[r],     a.y, w0.y);
            FFMA2(acc[8 + r], a.x, w1.x); FFMA2(acc[8 + r], a.y, w1.y);
        }
    }
}

// ---------------- fused Z+H pass: shared activation reads, two weight streams ----------------
// SA feeds accZ, SB feeds accH (SA==SB for the x-part: activation regs shared)
static __device__ __forceinline__ void gemm64x2_zh_sharedA(unsigned long long* accZ,
                                                           unsigned long long* accH,
                                                           const ulonglong2* __restrict__ Wz,
                                                           const ulonglong2* __restrict__ Wh,
                                                           const ulonglong2* S,
                                                           int c2, int rg8) {
    #pragma unroll 2
    for (int kk = 0; kk < 64; kk++) {
        ulonglong2 wz0 = Wz[kk * NH + c2];
        ulonglong2 wz1 = Wz[kk * NH + c2 + 128];
        ulonglong2 wh0 = Wh[kk * NH + c2];
        ulonglong2 wh1 = Wh[kk * NH + c2 + 128];
        #pragma unroll
        for (int r = 0; r < 8; r++) {
            ulonglong2 a = S[(rg8 + r) * 64 + kk];
            FFMA2(accZ[r],     a.x, wz0.x); FFMA2(accZ[r],     a.y, wz0.y);
            FFMA2(accZ[8 + r], a.x, wz1.x); FFMA2(accZ[8 + r], a.y, wz1.y);
            FFMA2(accH[r],     a.x, wh0.x); FFMA2(accH[r],     a.y, wh0.y);
            FFMA2(accH[8 + r], a.x, wh1.x); FFMA2(accH[8 + r], a.y, wh1.y);
        }
    }
}

// second half: accZ consumes SM, accH consumes SR
static __device__ __forceinline__ void gemm64x2_zh_split(unsigned long long* accZ,
                                                         unsigned long long* accH,
                                                         const ulonglong2* __restrict__ Wz,
                                                         const ulonglong2* __restrict__ Wh,
                                                         const ulonglong2* SM,
                                                         const ulonglong2* SR,
                                                         int c2, int rg8) {
    #pragma unroll 2
    for (int kk = 0; kk < 64; kk++) {
        ulonglong2 wz0 = Wz[kk * NH + c2];
        ulonglong2 wz1 = Wz[kk * NH + c2 + 128];
        ulonglong2 wh0 = Wh[kk * NH + c2];
        ulonglong2 wh1 = Wh[kk * NH + c2 + 128];
        #pragma unroll
        for (int r = 0; r < 8; r++) {
            ulonglong2 am = SM[(rg8 + r) * 64 + kk];
            ulonglong2 ar = SR[(rg8 + r) * 64 + kk];
            FFMA2(accZ[r],     am.x, wz0.x); FFMA2(accZ[r],     am.y, wz0.y);
            FFMA2(accZ[8 + r], am.x, wz1.x); FFMA2(accZ[8 + r], am.y, wz1.y);
            FFMA2(accH[r],     ar.x, wh0.x); FFMA2(accH[r],     ar.y, wh0.y);
            FFMA2(accH[8 + r], ar.x, wh1.x); FFMA2(accH[8 + r], ar.y, wh1.y);
        }
    }
}

// ---------------- persistent GRU: each CTA runs its full 15-step chain ----------------
// blockIdx < 256: fwd chain; >= 256: rev chain. Carries (m_prev, rm) live in smem.
__global__ __launch_bounds__(256, 2) void k_gru(const int* __restrict__ wid,
                                                const float* __restrict__ emb,
                                                const float* __restrict__ bz,
                                                const float* __restrict__ bh,
                                                const float* __restrict__ br) {
    __shared__ __align__(16) float sx[16][NH];   // x
    __shared__ __align__(16) float sm[16][NH];   // m_prev (then m)
    __shared__ __align__(16) float sr[16][NH];   // rm_prev (then rm)
    const int j = threadIdx.x;
    const int c2 = j & 127;
    const int rg8 = (j >> 7) * 8;
    const int dir = blockIdx.x >> 8;
    const int row0 = (blockIdx.x & 255) * 16;

    const float bz0 = bz[c2], bz1 = bz[c2 + 128];
    const float bh0 = bh[c2], bh1 = bh[c2 + 128];
    const float br0 = br[c2], br1 = br[c2 + 128];

    // initial stage: x at first source time; zero carries
    {
        int ts0 = dir ? 15 : 0;
        #pragma unroll
        for (int r = 0; r < 16; r++) {
            int b = row0 + r;
            int w = wid[b * NL + ts0];
            sx[r][j] = emb[w * NH + j];
            sm[r][j] = 0.f;
            sr[r][j] = 0.f;
        }
    }
    __syncthreads();

    const ulonglong2* SX = (const ulonglong2*)sx;
    const ulonglong2* SM = (const ulonglong2*)sm;
    const ulonglong2* SR = (const ulonglong2*)sr;

    for (int step = 0; step < STEPS; step++) {
        // ---- fused Z & H GEMMs ----
        unsigned long long accZ[16], accH[16];
        #pragma unroll
        for (int i = 0; i < 16; i++) { accZ[i] = 0ULL; accH[i] = 0ULL; }
        gemm64x2_zh_sharedA(accZ, accH, g_Wz4, g_Wh4, SX, c2, rg8);
        if (step > 0)   // carries are exactly zero at step 0: skipping is bit-identical
            gemm64x2_zh_split(accZ, accH, g_Wz4 + 64 * NH, g_Wh4 + 64 * NH, SM, SR, c2, rg8);

        // ---- epilogue: z, h, m ----
        float marr[16];
        {
            float* m_out = (dir == 0) ? &g_mfwd[step * NB * NH]
                                      : &g_mrev[(14 - step) * NB * NH];
            #pragma unroll
            for (int r = 0; r < 8; r++) {
                int row = rg8 + r;
                float2 tz0 = unpack2(accZ[r]);
                float2 tz1 = unpack2(accZ[8 + r]);
                float2 th0 = unpack2(accH[r]);
                float2 th1 = unpack2(accH[8 + r]);
                float z0 = 1.f / (1.f + expf(-(tz0.x + tz0.y + bz0)));
                float z1 = 1.f / (1.f + expf(-(tz1.x + tz1.y + bz1)));
                float h0 = tanhf(th0.x + th0.y + bh0);
                float h1 = tanhf(th1.x + th1.y + bh1);
                float m0 = (1.f - z0) * sm[row][c2]       + z0 * h0;
                float m1 = (1.f - z1) * sm[row][c2 + 128] + z1 * h1;
                marr[r] = m0; marr[8 + r] = m1;
                m_out[(row0 + row) * NH + c2]       = m0;
                m_out[(row0 + row) * NH + c2 + 128] = m1;
            }
        }
        __syncthreads();   // all gemm reads of sx/sm/sr complete
        if (step == STEPS - 1) break;

        // ---- restage: sx <- x_dst ; sm <- m (next m_prev, and R-gemm operand) ----
        {
            int tsd = dir ? 14 - step : step + 1;
            #pragma unroll
            for (int r = 0; r < 16; r++) {
                int b = row0 + r;
                int w = wid[b * NL + tsd];
                sx[r][j] = emb[w * NH + j];
            }
            #pragma unroll
            for (int r = 0; r < 8; r++) {
                sm[rg8 + r][c2]       = marr[r];
                sm[rg8 + r][c2 + 128] = marr[8 + r];
            }
        }
        __syncthreads();

        // ---- R = sigmoid(x_dst @ WrT + m @ UrT + br) ; sr <- r*m (sr dead since sync) ----
        {
            unsigned long long acc[16];
            #pragma unroll
            for (int i = 0; i < 16; i++) acc[i] = 0ULL;
            gemm64x2(acc, g_C4, SX, c2, rg8);
            gemm64x2(acc, g_C4 + 64 * NH, SM, c2, rg8);
            #pragma unroll
            for (int r = 0; r < 8; r++) {
                int row = rg8 + r;
                float2 t0 = unpack2(acc[r]);
                float2 t1 = unpack2(acc[8 + r]);
                float r0 = 1.f / (1.f + expf(-(t0.x + t0.y + br0)));
                float r1 = 1.f / (1.f + expf(-(t1.x + t1.y + br1)));
                sr[row][c2]       = r0 * marr[r];
                sr[row][c2 + 128] = r1 * marr[8 + r];
            }
        }
        __syncthreads();   // rm visible for next step's H gemm
    }
}

// ---------------- q path (unchanged) ----------------
__global__ __launch_bounds__(256, 2) void k_q(const int* __restrict__ wid,
                                              const float* __restrict__ tree,
                                              const float* __restrict__ Wb,
                                              const float* __restrict__ Wob) {
    extern __shared__ __align__(16) float smem[];
    float* hid = smem;                 // 16 x 256
    float* buf = smem + 16 * NH;       // 16 x 1024 logits (input phase: 16 x 320)
    __shared__ float s_red[16];
    __shared__ int s_cnt[16];
    const int j = threadIdx.x;
    const int c2 = j & 127;
    const int rg8 = (j >> 7) * 8;
    const int row0 = blockIdx.x * 16;
    const int t = row0 / NB;

    for (int r = 0; r < 16; r++) {
        int b = row0 + r - t * NB;
        for (int k = j; k < NH + NLAT; k += 256) {
            float v;
            if (k < NH) v = (t == 0) ? 0.f : g_mfwd[(t - 1) * NB * NH + b * NH + k];
            else        v = tree[b * NLAT + (k - NH)];
            buf[r * 320 + k] = v;
        }
    }
    __syncthreads();

    const ulonglong2* BUF = (const ulonglong2*)buf;   // row stride 80
    unsigned long long acc[16];
    #pragma unroll
    for (int i = 0; i < 16; i++) acc[i] = 0ULL;
    #pragma unroll 2
    for (int kk = 0; kk < 80; kk++) {
        ulonglong2 w0 = g_Wq4[kk * NH + c2];
        ulonglong2 w1 = g_Wq4[kk * NH + c2 + 128];
        #pragma unroll
        for (int r = 0; r < 8; r++) {
            ulonglong2 a = BUF[(rg8 + r) * 80 + kk];
            FFMA2(acc[r], a.x, w0.x);     FFMA2(acc[r], a.y, w0.y);
            FFMA2(acc[8 + r], a.x, w1.x); FFMA2(acc[8 + r], a.y, w1.y);
        }
    }
    {
        const float b0 = Wb[c2], b1 = Wb[c2 + 128];
        #pragma unroll
        for (int r = 0; r < 8; r++) {
            float2 t0 = unpack2(acc[r]);
            float2 t1 = unpack2(acc[8 + r]);
            hid[(rg8 + r) * NH + c2]       = fmaxf(t0.x + t0.y + b0, 0.f);
            hid[(rg8 + r) * NH + c2 + 128] = fmaxf(t1.x + t1.y + b1, 0.f);
        }
    }
    __syncthreads();

    const ulonglong2* HID = (const ulonglong2*)hid;   // row stride 64
    for (int g = 0; g < 4; g++) {
        int cA = g * 256 + c2;
        int cB = cA + 128;
        unsigned long long aq[16];
        #pragma unroll
        for (int i = 0; i < 16; i++) aq[i] = 0ULL;
        #pragma unroll 2
        for (int kk = 0; kk < 64; kk++) {
            ulonglong2 w0 = g_Wo4[kk * NVP + cA];
            ulonglong2 w1 = g_Wo4[kk * NVP + cB];
            #pragma unroll
            for (int r = 0; r < 8; r++) {
                ulonglong2 h = HID[(rg8 + r) * 64 + kk];
                FFMA2(aq[r], h.x, w0.x);     FFMA2(aq[r], h.y, w0.y);
                FFMA2(aq[8 + r], h.x, w1.x); FFMA2(aq[8 + r], h.y, w1.y);
            }
        }
        float wobA = (cA < NV) ? Wob[cA] : 0.f;
        float wobB = (cB < NV) ? Wob[cB] : 0.f;
        #pragma unroll
        for (int r = 0; r < 8; r++) {
            float2 t0 = unpack2(aq[r]);
            float2 t1 = unpack2(aq[8 + r]);
            buf[(rg8 + r) * NVP + cA] = t0.x + t0.y + wobA;
            buf[(rg8 + r) * NVP + cB] = t1.x + t1.y + wobB;
        }
    }
    __syncthreads();

    const int warp = j >> 5, lane = j & 31;
    for (int rr = 0; rr < 2; rr++) {
        int r = warp + rr * 8;
        float mx = -1e30f; int ai = 0;
        for (int c = lane; c < NV; c += 32) {
            float v = buf[r * NVP + c];
            if (v > mx) { mx = v; ai = c; }
        }
        for (int off = 16; off; off >>= 1) {
            float vo = __shfl_xor_sync(0xffffffffu, mx, off);
            int io = __shfl_xor_sync(0xffffffffu, ai, off);
            if (vo > mx || (vo == mx && io < ai)) { mx = vo; ai = io; }
        }
        float sum = 0.f;
        for (int c = lane; c < NV; c += 32) sum += expf(buf[r * NVP + c] - mx);
        for (int off = 16; off; off >>= 1) sum += __shfl_xor_sync(0xffffffffu, sum, off);
        if (lane == 0) {
            int b = row0 + r - t * NB;
            int qt = wid[b * NL + t];
            float logZ = mx + logf(sum);
            s_red[r] = logZ - buf[r * NVP + qt];
            s_cnt[r] = (ai == qt) ? 1 : 0;
        }
    }
    __syncthreads();
    if (j == 0) {
        double sum = 0.0; unsigned long long c = 0;
        for (int r = 0; r < 16; r++) { sum += (double)s_red[r]; c += (unsigned long long)s_cnt[r]; }
        atomicAdd(&g_qloss, sum);
        atomicAdd(&g_qcnt, c);
    }
}

// ---------------- p path (unchanged) ----------------
__global__ __launch_bounds__(256, 2) void k_p(const int* __restrict__ wid,
                                              const float* __restrict__ tree,
                                              const float* __restrict__ emb,
                                              const float* __restrict__ Ub,
                                              const float* __restrict__ Usw,
                                              const float* __restrict__ Usb) {
    extern __shared__ __align__(16) float smem[];
    float* a = smem;                 // 16 x 576
    float* hid = smem + 16 * 576;    // 16 x 256
    __shared__ float s_red[16];
    __shared__ int s_cnt[16];
    const int j = threadIdx.x;
    const int c2 = j & 127;
    const int rg8 = (j >> 7) * 8;
    const int row0 = blockIdx.x * 16;
    const int s = row0 / NB;
    const int tx = (s == 0) ? 0 : (s <= 15 ? s : 30 - s);

    for (int r = 0; r < 16; r++) {
        int b = row0 + r - s * NB;
        int w = wid[b * NL + tx];
        for (int k = j; k < 576; k += 256) {
            float v;
            if (k < 256) v = emb[w * NH + k];
            else if (k < 512) {
                int kk = k - 256;
                if (s == 0) v = 0.f;
                else if (s <= 15) v = g_mfwd[(s - 1) * NB * NH + b * NH + kk];
                else {
                    int jj = 30 - s;
                    v = g_mrev[jj * NB * NH + b * NH + kk];
                    if (jj > 0) v += g_mfwd[(jj - 1) * NB * NH + b * NH + kk];
                }
            } else v = tree[b * NLAT + (k - 512)];
            a[r * 576 + k] = v;
        }
    }
    __syncthreads();

    const ulonglong2* A2 = (const ulonglong2*)a;   // row stride 144
    unsigned long long acc[16];
    #pragma unroll
    for (int i = 0; i < 16; i++) acc[i] = 0ULL;
    #pragma unroll 2
    for (int kk = 0; kk < 144; kk++) {
        ulonglong2 w0 = g_Up4[kk * NH + c2];
        ulonglong2 w1 = g_Up4[kk * NH + c2 + 128];
        #pragma unroll
        for (int r = 0; r < 8; r++) {
            ulonglong2 av = A2[(rg8 + r) * 144 + kk];
            FFMA2(acc[r], av.x, w0.x);     FFMA2(acc[r], av.y, w0.y);
            FFMA2(acc[8 + r], av.x, w1.x); FFMA2(acc[8 + r], av.y, w1.y);
        }
    }
    {
        const float b0 = Ub[c2], b1 = Ub[c2 + 128];
        #pragma unroll
        for (int r = 0; r < 8; r++) {
            float2 t0 = unpack2(acc[r]);
            float2 t1 = unpack2(acc[8 + r]);
            hid[(rg8 + r) * NH + c2]       = fmaxf(t0.x + t0.y + b0, 0.f);
            hid[(rg8 + r) * NH + c2 + 128] = fmaxf(t1.x + t1.y + b1, 0.f);
        }
    }
    __syncthreads();

    const int warp = j >> 5, lane = j & 31;
    const float ptv = (s < 15) ? 1.f : 0.f;
    for (int rr = 0; rr < 2; rr++) {
        int r = warp + rr * 8;
        float ps = 0.f;
        for (int c = lane; c < NH; c += 32) ps += hid[r * NH + c] * Usw[c];
        for (int off = 16; off; off >>= 1) ps += __shfl_xor_sync(0xffffffffu, ps, off);
        if (lane == 0) {
            float p = ps + Usb[0];
            float loss = fmaxf(p, 0.f) + log1pf(expf(-fabsf(p))) - p * ptv;
            s_red[r] = loss;
            s_cnt[r] = ((p > 0.f) == (ptv > 0.5f)) ? 1 : 0;
        }
    }
    __syncthreads();
    if (j == 0) {
        double sum = 0.0; unsigned long long c = 0;
        for (int r = 0; r < 16; r++) { sum += (double)s_red[r]; c += (unsigned long long)s_cnt[r]; }
        atomicAdd(&g_ploss, sum);
        atomicAdd(&g_pcnt, c);
    }
}

// ---------------- finalize ----------------
__global__ void k_fin(float* __restrict__ out) {
    out[0] = (float)(g_qloss / (double)NB);
    out[1] = (float)(g_ploss / (double)NB);
    out[2] = (float)((double)g_qcnt / (double)(NL * NB));
    out[3] = (float)((double)g_pcnt / (double)((2 * NL - 1) * NB));
}

extern "C" void kernel_launch(void* const* d_in, const int* in_sizes, int n_in,
                              void* d_out, int out_size) {
    const int*   wid  = (const int*)  d_in[0];
    const float* tree = (const float*)d_in[1];
    const float* emb  = (const float*)d_in[2];
    const float* Wz_w = (const float*)d_in[3];
    const float* Wz_b = (const float*)d_in[4];
    const float* Wr_w = (const float*)d_in[5];
    const float* Ur_w = (const float*)d_in[6];
    const float* Ur_b = (const float*)d_in[7];
    const float* Wh_w = (const float*)d_in[8];
    const float* Wh_b = (const float*)d_in[9];
    const float* W_w  = (const float*)d_in[10];
    const float* W_b  = (const float*)d_in[11];
    const float* U_w  = (const float*)d_in[12];
    const float* U_b  = (const float*)d_in[13];
    const float* Wo_w = (const float*)d_in[14];
    const float* Wo_b = (const float*)d_in[15];
    const float* Us_w = (const float*)d_in[16];
    const float* Us_b = (const float*)d_in[17];
    float* out = (float*)d_out;

    const int q_smem = (16 * NH + 16 * NVP) * 4;       // 81920 B
    const int p_smem = (16 * 576 + 16 * NH) * 4;       // 53248 B
    cudaFuncSetAttribute(k_q, cudaFuncAttributeMaxDynamicSharedMemorySize, q_smem);
    cudaFuncSetAttribute(k_p, cudaFuncAttributeMaxDynamicSharedMemorySize, p_smem);

    k_init<<<1, 32>>>();

    const int total = 256 * 512 * 2 + 256 * 256 * 2 + 256 * 320 + 256 * 576 + NVP * 256;
    k_repack_all<<<(total + 255) / 256, 256>>>(Wz_w, Wh_w, Wr_w, Ur_w, W_w, U_w, Wo_w);

    // single persistent launch: 256 fwd chains + 256 rev chains
    k_gru<<<512, 256>>>(wid, emb, Wz_b, Wh_b, Ur_b);

    k_q<<<(NL * NB) / 16, 256, q_smem>>>(wid, tree, W_b, Wo_b);
    k_p<<<((2 * NL - 1) * NB) / 16, 256, p_smem>>>(wid, tree, emb, U_b, Us_w, Us_b);
    k_fin<<<1, 1>>>(out);
}

// round 17
// speedup vs baseline: 1.0670x; 1.0670x over previous
#include <cuda_runtime.h>
#include <cuda_bf16.h>
#include <math.h>

// Problem constants
static constexpr int NB = 4096;   // batch
static constexpr int NL = 16;     // seq length
static constexpr int NH = 256;    // hidden
static constexpr int NLAT = 64;   // latent
static constexpr int NV = 800;    // vocab
static constexpr int NVP = 1024;  // padded vocab
static constexpr int STEPS = NL - 1;  // 15
static constexpr int NQB = (NL * NB) / 16;        // 4096 q blocks
static constexpr int NPB = ((2 * NL - 1) * NB) / 16;  // 7936 p blocks

// ---------------- packed f32x2 helpers ----------------
#define FFMA2(acc, a, b) asm("fma.rn.f32x2 %0, %1, %2, %0;" : "+l"(acc) : "l"(a), "l"(b))

static __device__ __forceinline__ float2 unpack2(unsigned long long v) {
    float2 f;
    asm("mov.b64 {%0, %1}, %2;" : "=f"(f.x), "=f"(f.y) : "l"(v));
    return f;
}

// ---------------- device scratch (allocation-free) ----------------
__device__ float g_mfwd[STEPS * NB * NH];
__device__ float g_mrev[STEPS * NB * NH];
// pair-interleaved weights: ull2 index kk*J + col  (kk = k/4)
__device__ ulonglong2 g_Wz4[512 * 256 / 4];
__device__ ulonglong2 g_Wh4[512 * 256 / 4];
__device__ ulonglong2 g_C4 [512 * 256 / 4];   // [Wr ; Ur]
__device__ ulonglong2 g_Wq4[320 * 256 / 4];
__device__ ulonglong2 g_Up4[576 * 256 / 4];
__device__ ulonglong2 g_Wo4[256 * NVP / 4];   // padded, zeros beyond 800
__device__ double g_qloss, g_ploss;
__device__ unsigned long long g_qcnt, g_pcnt;

// ---------------- init ----------------
__global__ void k_init() {
    if (threadIdx.x == 0) {
        g_qloss = 0.0; g_ploss = 0.0; g_qcnt = 0ULL; g_pcnt = 0ULL;
    }
}

// ---------------- single-launch repack ----------------
__global__ void k_repack_all(const float* __restrict__ Wz, const float* __restrict__ Wh,
                             const float* __restrict__ Wr, const float* __restrict__ Ur,
                             const float* __restrict__ Wq, const float* __restrict__ Up,
                             const float* __restrict__ Wo) {
    int idx = blockIdx.x * blockDim.x + threadIdx.x;
    const int n0 = 256 * 512, n1 = n0 + 256 * 512, n2 = n1 + 256 * 256,
              n3 = n2 + 256 * 256, n4 = n3 + 256 * 320, n5 = n4 + 256 * 576,
              n6 = n5 + NVP * 256;
    if (idx >= n6) return;
    if (idx >= n5) {
        idx -= n5;
        int jcol = idx / 256, k = idx % 256;
        ((float*)g_Wo4)[((k >> 2) * NVP + jcol) * 4 + (k & 3)] =
            (jcol < NV) ? Wo[jcol * 256 + k] : 0.f;
        return;
    }
    const float* src; float* dst; int J, K, koff;
    if      (idx < n0) { src = Wz; dst = (float*)g_Wz4; J = 256; K = 512; koff = 0; }
    else if (idx < n1) { src = Wh; dst = (float*)g_Wh4; J = 256; K = 512; koff = 0; idx -= n0; }
    else if (idx < n2) { src = Wr; dst = (float*)g_C4;  J = 256; K = 256; koff = 0; idx -= n1; }
    else if (idx < n3) { src = Ur; dst = (float*)g_C4;  J = 256; K = 256; koff = 256; idx -= n2; }
    else if (idx < n4) { src = Wq; dst = (float*)g_Wq4; J = 256; K = 320; koff = 0; idx -= n3; }
    else               { src = Up; dst = (float*)g_Up4; J = 256; K = 576; koff = 0; idx -= n4; }
    int jcol = idx / K, k = idx % K;
    int kk = k + koff;
    dst[((kk >> 2) * J + jcol) * 4 + (kk & 3)] = src[jcol * K + k];
}

// ---------------- 64-kk GEMM block: 8 rows x 2 cols per thread (R9 proven) ----------------
static __device__ __forceinline__ void gemm64x2(unsigned long long* acc,
                                                const ulonglong2* __restrict__ W,
                                                const ulonglong2* S,
                                                int c2, int rg8) {
    #pragma unroll 2
    for (int kk = 0; kk < 64; kk++) {
        ulonglong2 w0 = W[kk * NH + c2];
        ulonglong2 w1 = W[kk * NH + c2 + 128];
        #pragma unroll
        for (int r = 0; r < 8; r++) {
            ulonglong2 a = S[(rg8 + r) * 64 + kk];
            FFMA2(acc[r],     a.x, w0.x); FFMA2(acc[r],     a.y, w0.y);
            FFMA2(acc[8 + r], a.x, w1.x); FFMA2(acc[8 + r], a.y, w1.y);
        }
    }
}

// ---------------- persistent GRU: each CTA runs its full 15-step chain ----------------
// blockIdx < 256: fwd chain; >= 256: rev chain. Carries (m_prev, rm) live in smem.
__global__ __launch_bounds__(256, 2) void k_gru(const int* __restrict__ wid,
                                                const float* __restrict__ emb,
                                                const float* __restrict__ bz,
                                                const float* __restrict__ bh,
                                                const float* __restrict__ br) {
    __shared__ __align__(16) float sx[16][NH];   // x
    __shared__ __align__(16) float sm[16][NH];   // m_prev (then m)
    __shared__ __align__(16) float sr[16][NH];   // rm_prev (then rm)
    const int j = threadIdx.x;
    const int c2 = j & 127;
    const int rg8 = (j >> 7) * 8;
    const int dir = blockIdx.x >> 8;
    const int row0 = (blockIdx.x & 255) * 16;

    const float bz0 = bz[c2], bz1 = bz[c2 + 128];
    const float bh0 = bh[c2], bh1 = bh[c2 + 128];
    const float br0 = br[c2], br1 = br[c2 + 128];

    // initial stage: x at first source time; zero carries
    {
        int ts0 = dir ? 15 : 0;
        #pragma unroll
        for (int r = 0; r < 16; r++) {
            int b = row0 + r;
            int w = wid[b * NL + ts0];
            sx[r][j] = emb[w * NH + j];
            sm[r][j] = 0.f;
            sr[r][j] = 0.f;
        }
    }
    __syncthreads();

    const ulonglong2* SX = (const ulonglong2*)sx;
    const ulonglong2* SM = (const ulonglong2*)sm;
    const ulonglong2* SR = (const ulonglong2*)sr;
    unsigned long long acc[16];

    for (int step = 0; step < STEPS; step++) {
        // ---- Z = sigmoid([x|m_prev] @ WzT + bz) ----
        #pragma unroll
        for (int i = 0; i < 16; i++) acc[i] = 0ULL;
        gemm64x2(acc, g_Wz4, SX, c2, rg8);
        if (step > 0)   // carries exactly zero at step 0: skipping is bit-identical
            gemm64x2(acc, g_Wz4 + 64 * NH, SM, c2, rg8);
        float zg[16];
        #pragma unroll
        for (int r = 0; r < 8; r++) {
            float2 t0 = unpack2(acc[r]);
            float2 t1 = unpack2(acc[8 + r]);
            zg[r]     = 1.f / (1.f + expf(-(t0.x + t0.y + bz0)));
            zg[8 + r] = 1.f / (1.f + expf(-(t1.x + t1.y + bz1)));
        }

        // ---- H = tanh([x|rm_prev] @ WhT + bh) ; m = (1-z)m_prev + z h ----
        #pragma unroll
        for (int i = 0; i < 16; i++) acc[i] = 0ULL;
        gemm64x2(acc, g_Wh4, SX, c2, rg8);
        if (step > 0)
            gemm64x2(acc, g_Wh4 + 64 * NH, SR, c2, rg8);
        float marr[16];
        {
            float* m_out = (dir == 0) ? &g_mfwd[step * NB * NH]
                                      : &g_mrev[(14 - step) * NB * NH];
            #pragma unroll
            for (int r = 0; r < 8; r++) {
                int row = rg8 + r;
                float2 t0 = unpack2(acc[r]);
                float2 t1 = unpack2(acc[8 + r]);
                float h0 = tanhf(t0.x + t0.y + bh0);
                float h1 = tanhf(t1.x + t1.y + bh1);
                float m0 = (1.f - zg[r])     * sm[row][c2]       + zg[r] * h0;
                float m1 = (1.f - zg[8 + r]) * sm[row][c2 + 128] + zg[8 + r] * h1;
                marr[r] = m0; marr[8 + r] = m1;
                m_out[(row0 + row) * NH + c2]       = m0;
                m_out[(row0 + row) * NH + c2 + 128] = m1;
            }
        }
        __syncthreads();   // all gemm reads of sx/sm/sr complete
        if (step == STEPS - 1) break;

        // ---- restage: sx <- x_dst ; sm <- m (next m_prev, and R-gemm operand) ----
        {
            int tsd = dir ? 14 - step : step + 1;
            #pragma unroll
            for (int r = 0; r < 16; r++) {
                int b = row0 + r;
                int w = wid[b * NL + tsd];
                sx[r][j] = emb[w * NH + j];
            }
            #pragma unroll
            for (int r = 0; r < 8; r++) {
                sm[rg8 + r][c2]       = marr[r];
                sm[rg8 + r][c2 + 128] = marr[8 + r];
            }
        }
        __syncthreads();

        // ---- R = sigmoid(x_dst @ WrT + m @ UrT + br) ; sr <- r*m (sr dead since sync) ----
        #pragma unroll
        for (int i = 0; i < 16; i++) acc[i] = 0ULL;
        gemm64x2(acc, g_C4, SX, c2, rg8);
        gemm64x2(acc, g_C4 + 64 * NH, SM, c2, rg8);
        #pragma unroll
        for (int r = 0; r < 8; r++) {
            int row = rg8 + r;
            float2 t0 = unpack2(acc[r]);
            float2 t1 = unpack2(acc[8 + r]);
            float r0 = 1.f / (1.f + expf(-(t0.x + t0.y + br0)));
            float r1 = 1.f / (1.f + expf(-(t1.x + t1.y + br1)));
            sr[row][c2]       = r0 * marr[r];
            sr[row][c2 + 128] = r1 * marr[8 + r];
        }
        __syncthreads();   // rm visible for next step's H gemm
    }
}

// ---------------- merged q + p kernel: blockIdx < NQB -> q, else p ----------------
__global__ __launch_bounds__(256, 2) void k_qp(const int* __restrict__ wid,
                                               const float* __restrict__ tree,
                                               const float* __restrict__ emb,
                                               const float* __restrict__ Wb,
                                               const float* __restrict__ Wob,
                                               const float* __restrict__ Ub,
                                               const float* __restrict__ Usw,
                                               const float* __restrict__ Usb) {
    extern __shared__ __align__(16) float smem[];
    __shared__ float s_red[16];
    __shared__ int s_cnt[16];
    const int j = threadIdx.x;
    const int c2 = j & 127;
    const int rg8 = (j >> 7) * 8;
    const int warp = j >> 5, lane = j & 31;

    if (blockIdx.x < NQB) {
        // ================= q path =================
        float* hid = smem;                 // 16 x 256
        float* buf = smem + 16 * NH;       // 16 x 1024 logits (input phase: 16 x 320)
        const int row0 = blockIdx.x * 16;
        const int t = row0 / NB;

        for (int r = 0; r < 16; r++) {
            int b = row0 + r - t * NB;
            for (int k = j; k < NH + NLAT; k += 256) {
                float v;
                if (k < NH) v = (t == 0) ? 0.f : g_mfwd[(t - 1) * NB * NH + b * NH + k];
                else        v = tree[b * NLAT + (k - NH)];
                buf[r * 320 + k] = v;
            }
        }
        __syncthreads();

        const ulonglong2* BUF = (const ulonglong2*)buf;   // row stride 80
        unsigned long long acc[16];
        #pragma unroll
        for (int i = 0; i < 16; i++) acc[i] = 0ULL;
        #pragma unroll 4
        for (int kk = 0; kk < 80; kk++) {
            ulonglong2 w0 = g_Wq4[kk * NH + c2];
            ulonglong2 w1 = g_Wq4[kk * NH + c2 + 128];
            #pragma unroll
            for (int r = 0; r < 8; r++) {
                ulonglong2 a = BUF[(rg8 + r) * 80 + kk];
                FFMA2(acc[r], a.x, w0.x);     FFMA2(acc[r], a.y, w0.y);
                FFMA2(acc[8 + r], a.x, w1.x); FFMA2(acc[8 + r], a.y, w1.y);
            }
        }
        {
            const float b0 = Wb[c2], b1 = Wb[c2 + 128];
            #pragma unroll
            for (int r = 0; r < 8; r++) {
                float2 t0 = unpack2(acc[r]);
                float2 t1 = unpack2(acc[8 + r]);
                hid[(rg8 + r) * NH + c2]       = fmaxf(t0.x + t0.y + b0, 0.f);
                hid[(rg8 + r) * NH + c2 + 128] = fmaxf(t1.x + t1.y + b1, 0.f);
            }
        }
        __syncthreads();

        const ulonglong2* HID = (const ulonglong2*)hid;   // row stride 64
        for (int g = 0; g < 4; g++) {
            int cA = g * 256 + c2;
            int cB = cA + 128;
            unsigned long long aq[16];
            #pragma unroll
            for (int i = 0; i < 16; i++) aq[i] = 0ULL;
            #pragma unroll 4
            for (int kk = 0; kk < 64; kk++) {
                ulonglong2 w0 = g_Wo4[kk * NVP + cA];
                ulonglong2 w1 = g_Wo4[kk * NVP + cB];
                #pragma unroll
                for (int r = 0; r < 8; r++) {
                    ulonglong2 h = HID[(rg8 + r) * 64 + kk];
                    FFMA2(aq[r], h.x, w0.x);     FFMA2(aq[r], h.y, w0.y);
                    FFMA2(aq[8 + r], h.x, w1.x); FFMA2(aq[8 + r], h.y, w1.y);
                }
            }
            float wobA = (cA < NV) ? Wob[cA] : 0.f;
            float wobB = (cB < NV) ? Wob[cB] : 0.f;
            #pragma unroll
            for (int r = 0; r < 8; r++) {
                float2 t0 = unpack2(aq[r]);
                float2 t1 = unpack2(aq[8 + r]);
                buf[(rg8 + r) * NVP + cA] = t0.x + t0.y + wobA;
                buf[(rg8 + r) * NVP + cB] = t1.x + t1.y + wobB;
            }
        }
        __syncthreads();

        for (int rr = 0; rr < 2; rr++) {
            int r = warp + rr * 8;
            float mx = -1e30f; int ai = 0;
            for (int c = lane; c < NV; c += 32) {
                float v = buf[r * NVP + c];
                if (v > mx) { mx = v; ai = c; }
            }
            for (int off = 16; off; off >>= 1) {
                float vo = __shfl_xor_sync(0xffffffffu, mx, off);
                int io = __shfl_xor_sync(0xffffffffu, ai, off);
                if (vo > mx || (vo == mx && io < ai)) { mx = vo; ai = io; }
            }
            float sum = 0.f;
            for (int c = lane; c < NV; c += 32) sum += expf(buf[r * NVP + c] - mx);
            for (int off = 16; off; off >>= 1) sum += __shfl_xor_sync(0xffffffffu, sum, off);
            if (lane == 0) {
                int b = row0 + r - t * NB;
                int qt = wid[b * NL + t];
                float logZ = mx + logf(sum);
                s_red[r] = logZ - buf[r * NVP + qt];
                s_cnt[r] = (ai == qt) ? 1 : 0;
            }
        }
        __syncthreads();
        if (j == 0) {
            double sum = 0.0; unsigned long long c = 0;
            for (int r = 0; r < 16; r++) { sum += (double)s_red[r]; c += (unsigned long long)s_cnt[r]; }
            atomicAdd(&g_qloss, sum);
            atomicAdd(&g_qcnt, c);
        }
    } else {
        // ================= p path =================
        float* a = smem;                 // 16 x 576
        float* hid = smem + 16 * 576;    // 16 x 256
        const int row0 = (blockIdx.x - NQB) * 16;
        const int s = row0 / NB;
        const int tx = (s == 0) ? 0 : (s <= 15 ? s : 30 - s);

        for (int r = 0; r < 16; r++) {
            int b = row0 + r - s * NB;
            int w = wid[b * NL + tx];
            for (int k = j; k < 576; k += 256) {
                float v;
                if (k < 256) v = emb[w * NH + k];
                else if (k < 512) {
                    int kk = k - 256;
                    if (s == 0) v = 0.f;
                    else if (s <= 15) v = g_mfwd[(s - 1) * NB * NH + b * NH + kk];
                    else {
                        int jj = 30 - s;
                        v = g_mrev[jj * NB * NH + b * NH + kk];
                        if (jj > 0) v += g_mfwd[(jj - 1) * NB * NH + b * NH + kk];
                    }
                } else v = tree[b * NLAT + (k - 512)];
                a[r * 576 + k] = v;
            }
        }
        __syncthreads();

        const ulonglong2* A2 = (const ulonglong2*)a;   // row stride 144
        unsigned long long acc[16];
        #pragma unroll
        for (int i = 0; i < 16; i++) acc[i] = 0ULL;
        #pragma unroll 4
        for (int kk = 0; kk < 144; kk++) {
            ulonglong2 w0 = g_Up4[kk * NH + c2];
            ulonglong2 w1 = g_Up4[kk * NH + c2 + 128];
            #pragma unroll
            for (int r = 0; r < 8; r++) {
                ulonglong2 av = A2[(rg8 + r) * 144 + kk];
                FFMA2(acc[r], av.x, w0.x);     FFMA2(acc[r], av.y, w0.y);
                FFMA2(acc[8 + r], av.x, w1.x); FFMA2(acc[8 + r], av.y, w1.y);
            }
        }
        {
            const float b0 = Ub[c2], b1 = Ub[c2 + 128];
            #pragma unroll
            for (int r = 0; r < 8; r++) {
                float2 t0 = unpack2(acc[r]);
                float2 t1 = unpack2(acc[8 + r]);
                hid[(rg8 + r) * NH + c2]       = fmaxf(t0.x + t0.y + b0, 0.f);
                hid[(rg8 + r) * NH + c2 + 128] = fmaxf(t1.x + t1.y + b1, 0.f);
            }
        }
        __syncthreads();

        const float ptv = (s < 15) ? 1.f : 0.f;
        for (int rr = 0; rr < 2; rr++) {
            int r = warp + rr * 8;
            float ps = 0.f;
            for (int c = lane; c < NH; c += 32) ps += hid[r * NH + c] * Usw[c];
            for (int off = 16; off; off >>= 1) ps += __shfl_xor_sync(0xffffffffu, ps, off);
            if (lane == 0) {
                float p = ps + Usb[0];
                float loss = fmaxf(p, 0.f) + log1pf(expf(-fabsf(p))) - p * ptv;
                s_red[r] = loss;
                s_cnt[r] = ((p > 0.f) == (ptv > 0.5f)) ? 1 : 0;
            }
        }
        __syncthreads();
        if (j == 0) {
            double sum = 0.0; unsigned long long c = 0;
            for (int r = 0; r < 16; r++) { sum += (double)s_red[r]; c += (unsigned long long)s_cnt[r]; }
            atomicAdd(&g_ploss, sum);
            atomicAdd(&g_pcnt, c);
        }
    }
}

// ---------------- finalize ----------------
__global__ void k_fin(float* __restrict__ out) {
    out[0] = (float)(g_qloss / (double)NB);
    out[1] = (float)(g_ploss / (double)NB);
    out[2] = (float)((double)g_qcnt / (double)(NL * NB));
    out[3] = (float)((double)g_pcnt / (double)((2 * NL - 1) * NB));
}

extern "C" void kernel_launch(void* const* d_in, const int* in_sizes, int n_in,
                              void* d_out, int out_size) {
    const int*   wid  = (const int*)  d_in[0];
    const float* tree = (const float*)d_in[1];
    const float* emb  = (const float*)d_in[2];
    const float* Wz_w = (const float*)d_in[3];
    const float* Wz_b = (const float*)d_in[4];
    const float* Wr_w = (const float*)d_in[5];
    const float* Ur_w = (const float*)d_in[6];
    const float* Ur_b = (const float*)d_in[7];
    const float* Wh_w = (const float*)d_in[8];
    const float* Wh_b = (const float*)d_in[9];
    const float* W_w  = (const float*)d_in[10];
    const float* W_b  = (const float*)d_in[11];
    const float* U_w  = (const float*)d_in[12];
    const float* U_b  = (const float*)d_in[13];
    const float* Wo_w = (const float*)d_in[14];
    const float* Wo_b = (const float*)d_in[15];
    const float* Us_w = (const float*)d_in[16];
    const float* Us_b = (const float*)d_in[17];
    float* out = (float*)d_out;

    const int qp_smem = (16 * NH + 16 * NVP) * 4;      // 81920 B (max of q/p needs)
    cudaFuncSetAttribute(k_qp, cudaFuncAttributeMaxDynamicSharedMemorySize, qp_smem);

    k_init<<<1, 32>>>();

    const int total = 256 * 512 * 2 + 256 * 256 * 2 + 256 * 320 + 256 * 576 + NVP * 256;
    k_repack_all<<<(total + 255) / 256, 256>>>(Wz_w, Wh_w, Wr_w, Ur_w, W_w, U_w, Wo_w);

    // single persistent launch: 256 fwd chains + 256 rev chains
    k_gru<<<512, 256>>>(wid, emb, Wz_b, Wh_b, Ur_b);

    // merged q + p launch
    k_qp<<<NQB + NPB, 256, qp_smem>>>(wid, tree, emb, W_b, Wo_b, U_b, Us_w, Us_b);
    k_fin<<<1, 1>>>(out);
}